// round 2
// baseline (speedup 1.0000x reference)
#include <cuda_runtime.h>
#include <math.h>

#define NN 50000
#define EE 400000
#define FF 128
#define F3 384
#define NRBF 20

typedef unsigned long long u64;

// ---------------- f32x2 packed helpers ----------------
__device__ __forceinline__ u64 pk2(float a, float b) {
    u64 r; asm("mov.b64 %0,{%1,%2};" : "=l"(r) : "f"(a), "f"(b)); return r;
}
__device__ __forceinline__ u64 pkdup(float a) {
    u64 r; asm("mov.b64 %0,{%1,%1};" : "=l"(r) : "f"(a)); return r;
}
__device__ __forceinline__ float2 upk(u64 v) {
    float2 f; asm("mov.b64 {%0,%1},%2;" : "=f"(f.x), "=f"(f.y) : "l"(v)); return f;
}
__device__ __forceinline__ u64 f2fma(u64 a, u64 b, u64 c) {
    u64 d; asm("fma.rn.f32x2 %0,%1,%2,%3;" : "=l"(d) : "l"(a), "l"(b), "l"(c)); return d;
}
__device__ __forceinline__ u64 f2mul(u64 a, u64 b) {
    u64 d; asm("mul.rn.f32x2 %0,%1,%2;" : "=l"(d) : "l"(a), "l"(b)); return d;
}
__device__ __forceinline__ u64 f2add(u64 a, u64 b) {
    u64 d; asm("add.rn.f32x2 %0,%1,%2;" : "=l"(d) : "l"(a), "l"(b)); return d;
}

// ---------------- scratch ----------------
__device__ float  g_phi[NN * F3];
__device__ float  g_h[NN * FF];
__device__ float4 g_rbf4[EE * 5];    // AoS: 20 rbf values per CSR position
__device__ float4 g_dirn4[EE];       // dirn per CSR position (w unused)
__device__ int    g_cnt[NN];
__device__ int    g_off[NN + 1];
__device__ int    g_cur[NN];
__device__ int    g_order[EE];

// ---------------- CSR build ----------------
__global__ void k_zero() {
    int i = blockIdx.x * blockDim.x + threadIdx.x;
    if (i < NN) g_cnt[i] = 0;
}

__global__ void k_hist(const float* __restrict__ r) {
    int e = blockIdx.x * blockDim.x + threadIdx.x;
    if (e < EE) {
        int j = (int)r[e * 5 + 1];
        atomicAdd(&g_cnt[j], 1);
    }
}

__global__ void k_scan() {
    __shared__ int part[1024];
    int t = threadIdx.x;
    const int CH = (NN + 1023) / 1024;
    int base = t * CH, sum = 0;
    for (int i = 0; i < CH; i++) {
        int idx = base + i;
        if (idx < NN) sum += g_cnt[idx];
    }
    part[t] = sum;
    __syncthreads();
    for (int off = 1; off < 1024; off <<= 1) {
        int v = (t >= off) ? part[t - off] : 0;
        __syncthreads();
        part[t] += v;
        __syncthreads();
    }
    int run = (t > 0) ? part[t - 1] : 0;
    for (int i = 0; i < CH; i++) {
        int idx = base + i;
        if (idx < NN) {
            g_off[idx] = run;
            g_cur[idx] = run;
            run += g_cnt[idx];
        }
    }
    if (t == 1023) g_off[NN] = part[1023];
}

__global__ void k_fill(const float* __restrict__ r) {
    int e = blockIdx.x * blockDim.x + threadIdx.x;
    if (e < EE) {
        int j = (int)r[e * 5 + 1];
        int pos = atomicAdd(&g_cur[j], 1);
        g_order[pos] = e;
    }
}

__global__ void k_sortlists() {
    int n = blockIdx.x * blockDim.x + threadIdx.x;
    if (n >= NN) return;
    int s0 = g_off[n], s1 = g_off[n + 1];
    for (int i = s0 + 1; i < s1; i++) {
        int key = g_order[i];
        int j = i - 1;
        while (j >= s0 && g_order[j] > key) {
            g_order[j + 1] = g_order[j];
            j--;
        }
        g_order[j + 1] = key;
    }
}

// ---------------- per-edge precompute (sin recurrence) ----------------
__global__ void k_edge(const float* __restrict__ r) {
    int p = blockIdx.x * blockDim.x + threadIdx.x;
    if (p >= EE) return;
    int eid = g_order[p];
    float rx = r[eid * 5 + 2];
    float ry = r[eid * 5 + 3];
    float rz = r[eid * 5 + 4];
    float z = fabsf(rz);
    float inv = 1.0f / (z + 1e-8f);
    float th = 0.6283185307179586f * z;   // pi/5 * z
    float s, c;
    sincosf(th, &s, &c);
    float twoc = 2.0f * c;
    float buf[NRBF];
    float skm = 0.0f, sk = s;
#pragma unroll
    for (int k = 0; k < NRBF; k++) {
        buf[k] = sk * inv;
        float nxt = fmaf(twoc, sk, -skm);
        skm = sk; sk = nxt;
    }
#pragma unroll
    for (int i = 0; i < 5; i++)
        g_rbf4[p * 5 + i] = make_float4(buf[4 * i], buf[4 * i + 1], buf[4 * i + 2], buf[4 * i + 3]);
    float nrm = sqrtf(rx * rx + ry * ry + rz * rz);
    float invn = 1.0f / (nrm + 1e-8f);
    g_dirn4[p] = make_float4(rx * invn, ry * invn, rz * invn, 0.0f);
}

// ---------------- fp32 GEMM with packed f32x2 inner loop ----------------
template <bool SILU>
__global__ void __launch_bounds__(256) k_gemm(const float* __restrict__ A,
                                              const float* __restrict__ B,
                                              const float* __restrict__ bias,
                                              float* __restrict__ C,
                                              int M, int N, int K) {
    __shared__ float As[16][132];
    __shared__ float Bs[16][64];
    int t = threadIdx.x;
    int rowBase = blockIdx.y * 128;
    int colBase = blockIdx.x * 64;
    int tm = (t >> 4) << 3;
    int tn = (t & 15) << 2;
    u64 acc[8][2];
#pragma unroll
    for (int i = 0; i < 8; i++) { acc[i][0] = 0ull; acc[i][1] = 0ull; }
    int ar = t >> 2;
    int ak = (t & 3) << 2;
    int brow = t >> 4;
    int bcol = (t & 15) << 2;

    for (int kt = 0; kt < K; kt += 16) {
#pragma unroll
        for (int h = 0; h < 2; h++) {
            int row = ar + h * 64;
            int grow = rowBase + row;
            float4 a4 = make_float4(0.f, 0.f, 0.f, 0.f);
            if (grow < M) a4 = *(const float4*)&A[grow * K + kt + ak];
            As[ak + 0][row] = a4.x;
            As[ak + 1][row] = a4.y;
            As[ak + 2][row] = a4.z;
            As[ak + 3][row] = a4.w;
        }
        *(float4*)&Bs[brow][bcol] = *(const float4*)&B[(kt + brow) * N + colBase + bcol];
        __syncthreads();
#pragma unroll
        for (int k = 0; k < 16; k++) {
            float4 a0 = *(float4*)&As[k][tm];
            float4 a1v = *(float4*)&As[k][tm + 4];
            float4 b0 = *(float4*)&Bs[k][tn];
            u64 bb0 = pk2(b0.x, b0.y);
            u64 bb1 = pk2(b0.z, b0.w);
            float a[8] = {a0.x, a0.y, a0.z, a0.w, a1v.x, a1v.y, a1v.z, a1v.w};
#pragma unroll
            for (int i = 0; i < 8; i++) {
                u64 aa = pkdup(a[i]);
                acc[i][0] = f2fma(aa, bb0, acc[i][0]);
                acc[i][1] = f2fma(aa, bb1, acc[i][1]);
            }
        }
        __syncthreads();
    }
#pragma unroll
    for (int i = 0; i < 8; i++) {
        int grow = rowBase + tm + i;
        if (grow < M) {
            float2 c0 = upk(acc[i][0]);
            float2 c1 = upk(acc[i][1]);
            float bv[4] = {c0.x, c0.y, c1.x, c1.y};
            float4 o;
#pragma unroll
            for (int j = 0; j < 4; j++) {
                float val = bv[j] + bias[colBase + tn + j];
                if (SILU) val = val / (1.0f + __expf(-val));
                bv[j] = val;
            }
            o.x = bv[0]; o.y = bv[1]; o.z = bv[2]; o.w = bv[3];
            *(float4*)&C[grow * N + colBase + tn] = o;
        }
    }
}

// ---------------- packed cutoff weight ----------------
struct CutC {
    u64 c01, mag, nmag, neg1, half;
    u64 k[7];
};
__device__ __forceinline__ u64 cutW2(u64 X, const CutC& cc) {
    u64 u = f2mul(X, cc.c01);                 // x/10
    u64 tt = f2add(u, cc.mag);
    u64 rr = f2add(tt, cc.nmag);              // rint(u)
    u = f2fma(rr, cc.neg1, u);                // u - rint(u)  in [-0.5,0.5]
    u64 w = f2mul(u, u);
    u64 c = cc.k[0];
#pragma unroll
    for (int i = 1; i < 7; i++) c = f2fma(c, w, cc.k[i]);
    u64 Wv = f2fma(c, cc.half, cc.half);      // 0.5*(cos+1)
    // cutoff mask (x < 5)
    float2 xv = upk(X);
    float2 wv = upk(Wv);
    wv.x = (xv.x < 5.0f) ? wv.x : 0.0f;
    wv.y = (xv.y < 5.0f) ? wv.y : 0.0f;
    return pk2(wv.x, wv.y);
}

// ---------------- main per-node kernel (64 threads, feature pairs, all f32x2) ----------------
__global__ void __launch_bounds__(64) k_main(const float* __restrict__ v,
                                             const float* __restrict__ Wr,
                                             const float* __restrict__ br,
                                             float* __restrict__ out) {
    int t = threadIdx.x;
    int f0 = 2 * t, f1 = 2 * t + 1;

    u64 wr0[NRBF], wr1[NRBF], wr2[NRBF];
#pragma unroll
    for (int k = 0; k < NRBF; k++) {
        wr0[k] = pk2(Wr[k * F3 + f0],          Wr[k * F3 + f1]);
        wr1[k] = pk2(Wr[k * F3 + FF + f0],     Wr[k * F3 + FF + f1]);
        wr2[k] = pk2(Wr[k * F3 + 2 * FF + f0], Wr[k * F3 + 2 * FF + f1]);
    }
    u64 br0 = pk2(br[f0], br[f1]);
    u64 br1 = pk2(br[FF + f0], br[FF + f1]);
    u64 br2 = pk2(br[2 * FF + f0], br[2 * FF + f1]);

    CutC cc;
    cc.c01  = pkdup(0.1f);
    cc.mag  = pkdup(12582912.0f);     // 1.5*2^23
    cc.nmag = pkdup(-12582912.0f);
    cc.neg1 = pkdup(-1.0f);
    cc.half = pkdup(0.5f);
    cc.k[0] = pkdup(-1.714374f);
    cc.k[1] = pkdup(7.903536f);
    cc.k[2] = pkdup(-26.425825f);
    cc.k[3] = pkdup(60.244630f);
    cc.k[4] = pkdup(-85.456806f);
    cc.k[5] = pkdup(64.939394f);
    cc.k[6] = pkdup(-19.739209f);
    // final Horner step constant +1.0 folded below
    u64 one = pkdup(1.0f);

    for (int n = blockIdx.x; n < NN; n += gridDim.x) {
        int p0 = g_off[n], p1e = g_off[n + 1];
        u64 accA = 0ull, accB = 0ull;
        u64 bx = 0ull, by = 0ull, bz = 0ull;
        for (int p = p0; p < p1e; p++) {
            const float4* rp = &g_rbf4[p * 5];
            float4 q0 = rp[0], q1 = rp[1], q2 = rp[2], q3 = rp[3], q4 = rp[4];
            float rb[NRBF] = {q0.x, q0.y, q0.z, q0.w, q1.x, q1.y, q1.z, q1.w,
                              q2.x, q2.y, q2.z, q2.w, q3.x, q3.y, q3.z, q3.w,
                              q4.x, q4.y, q4.z, q4.w};
            u64 x0 = br0, x1 = br1, x2 = br2;
#pragma unroll
            for (int k = 0; k < NRBF; k++) {
                u64 rr = pkdup(rb[k]);
                x0 = f2fma(rr, wr0[k], x0);
                x1 = f2fma(rr, wr1[k], x1);
                x2 = f2fma(rr, wr2[k], x2);
            }
            // cutW with the +1.0 Horner tail: c poly then W = 0.5*((c*w+1)+1)?  No:
            // full poly: P(w) = (((k0*w+k1)w+...+k6)w + 1);  W = 0.5*P + 0.5
            u64 W0, W1v, W2v;
            {
                // inline to reuse the "one" constant for final Horner step
                u64 X = x0;
                u64 u = f2mul(X, cc.c01);
                u64 tt = f2add(u, cc.mag);
                u64 rr2 = f2add(tt, cc.nmag);
                u = f2fma(rr2, cc.neg1, u);
                u64 w = f2mul(u, u);
                u64 c = cc.k[0];
#pragma unroll
                for (int i = 1; i < 7; i++) c = f2fma(c, w, cc.k[i]);
                c = f2fma(c, w, one);
                u64 Wv = f2fma(c, cc.half, cc.half);
                float2 xv = upk(X); float2 wv = upk(Wv);
                wv.x = (xv.x < 5.0f) ? wv.x : 0.0f;
                wv.y = (xv.y < 5.0f) ? wv.y : 0.0f;
                W0 = pk2(wv.x, wv.y);
            }
            {
                u64 X = x1;
                u64 u = f2mul(X, cc.c01);
                u64 tt = f2add(u, cc.mag);
                u64 rr2 = f2add(tt, cc.nmag);
                u = f2fma(rr2, cc.neg1, u);
                u64 w = f2mul(u, u);
                u64 c = cc.k[0];
#pragma unroll
                for (int i = 1; i < 7; i++) c = f2fma(c, w, cc.k[i]);
                c = f2fma(c, w, one);
                u64 Wv = f2fma(c, cc.half, cc.half);
                float2 xv = upk(X); float2 wv = upk(Wv);
                wv.x = (xv.x < 5.0f) ? wv.x : 0.0f;
                wv.y = (xv.y < 5.0f) ? wv.y : 0.0f;
                W1v = pk2(wv.x, wv.y);
            }
            {
                u64 X = x2;
                u64 u = f2mul(X, cc.c01);
                u64 tt = f2add(u, cc.mag);
                u64 rr2 = f2add(tt, cc.nmag);
                u = f2fma(rr2, cc.neg1, u);
                u64 w = f2mul(u, u);
                u64 c = cc.k[0];
#pragma unroll
                for (int i = 1; i < 7; i++) c = f2fma(c, w, cc.k[i]);
                c = f2fma(c, w, one);
                u64 Wv = f2fma(c, cc.half, cc.half);
                float2 xv = upk(X); float2 wv = upk(Wv);
                wv.x = (xv.x < 5.0f) ? wv.x : 0.0f;
                wv.y = (xv.y < 5.0f) ? wv.y : 0.0f;
                W2v = pk2(wv.x, wv.y);
            }
            float4 dn = g_dirn4[p];
            accA = f2add(accA, W0);
            accB = f2add(accB, W1v);
            bx = f2fma(W2v, pkdup(dn.x), bx);
            by = f2fma(W2v, pkdup(dn.y), by);
            bz = f2fma(W2v, pkdup(dn.z), bz);
        }
        float2 aA = upk(accA);
        float2 aB = upk(accB);
        float2 bxv = upk(bx), byv = upk(by), bzv = upk(bz);

        float2 ph1 = *(const float2*)&g_phi[n * F3 + f0];
        float2 ph2 = *(const float2*)&g_phi[n * F3 + FF + f0];
        float2 ph3 = *(const float2*)&g_phi[n * F3 + 2 * FF + f0];

        int nf0 = n * FF + f0;
        // feature f0
        {
            float s1v = ph1.x * aA.x;
            float vx = v[nf0 * 3 + 0], vy = v[nf0 * 3 + 1], vz = v[nf0 * 3 + 2];
            out[nf0 * 3 + 0] = fmaf(vx, s1v, ph3.x * bxv.x);
            out[nf0 * 3 + 1] = fmaf(vy, s1v, ph3.x * byv.x);
            out[nf0 * 3 + 2] = fmaf(vz, s1v, ph3.x * bzv.x);
            out[NN * F3 + nf0] = ph2.x * aB.x;
        }
        // feature f1
        {
            int nf1 = nf0 + 1;
            float s1v = ph1.y * aA.y;
            float vx = v[nf1 * 3 + 0], vy = v[nf1 * 3 + 1], vz = v[nf1 * 3 + 2];
            out[nf1 * 3 + 0] = fmaf(vx, s1v, ph3.y * bxv.y);
            out[nf1 * 3 + 1] = fmaf(vy, s1v, ph3.y * byv.y);
            out[nf1 * 3 + 2] = fmaf(vz, s1v, ph3.y * bzv.y);
            out[NN * F3 + nf1] = ph2.y * aB.y;
        }
    }
}

// ---------------- launch ----------------
extern "C" void kernel_launch(void* const* d_in, const int* in_sizes, int n_in,
                              void* d_out, int out_size) {
    (void)in_sizes; (void)n_in; (void)out_size;
    const float* v  = (const float*)d_in[0];
    const float* s  = (const float*)d_in[1];
    const float* r  = (const float*)d_in[2];
    const float* W1 = (const float*)d_in[3];
    const float* b1 = (const float*)d_in[4];
    const float* W2 = (const float*)d_in[5];
    const float* b2 = (const float*)d_in[6];
    const float* Wr = (const float*)d_in[7];
    const float* br = (const float*)d_in[8];
    float* out = (float*)d_out;

    void* q;
    cudaGetSymbolAddress(&q, g_h);
    float* hptr = (float*)q;
    cudaGetSymbolAddress(&q, g_phi);
    float* pptr = (float*)q;

    k_zero<<<(NN + 255) / 256, 256>>>();
    k_hist<<<(EE + 255) / 256, 256>>>(r);
    k_scan<<<1, 1024>>>();
    k_fill<<<(EE + 255) / 256, 256>>>(r);
    k_sortlists<<<(NN + 127) / 128, 128>>>();
    k_edge<<<(EE + 127) / 128, 128>>>(r);
    {
        dim3 g1(FF / 64, (NN + 127) / 128);
        k_gemm<true><<<g1, 256>>>(s, W1, b1, hptr, NN, FF, FF);
        dim3 g2(F3 / 64, (NN + 127) / 128);
        k_gemm<false><<<g2, 256>>>(hptr, W2, b2, pptr, NN, F3, FF);
    }
    k_main<<<NN, 64>>>(v, Wr, br, out);
}

// round 3
// speedup vs baseline: 1.3267x; 1.3267x over previous
#include <cuda_runtime.h>
#include <math.h>

#define NN 50000
#define EE 400000
#define FF 128
#define F3 384
#define NRBF 20
#define EPAD (EE + NN)          // CSR positions incl. per-node even-alignment pads
#define EP 450560               // padded stride for rbf/dirn arrays (>= EPAD, 64-aligned)

typedef unsigned long long u64;

// ---------------- f32x2 packed helpers ----------------
__device__ __forceinline__ u64 pk2(float a, float b) {
    u64 r; asm("mov.b64 %0,{%1,%2};" : "=l"(r) : "f"(a), "f"(b)); return r;
}
__device__ __forceinline__ u64 pkdup(float a) {
    u64 r; asm("mov.b64 %0,{%1,%1};" : "=l"(r) : "f"(a)); return r;
}
__device__ __forceinline__ float2 upk(u64 v) {
    float2 f; asm("mov.b64 {%0,%1},%2;" : "=f"(f.x), "=f"(f.y) : "l"(v)); return f;
}
__device__ __forceinline__ u64 f2fma(u64 a, u64 b, u64 c) {
    u64 d; asm("fma.rn.f32x2 %0,%1,%2,%3;" : "=l"(d) : "l"(a), "l"(b), "l"(c)); return d;
}
__device__ __forceinline__ u64 f2add(u64 a, u64 b) {
    u64 d; asm("add.rn.f32x2 %0,%1,%2;" : "=l"(d) : "l"(a), "l"(b)); return d;
}

// ---------------- scratch ----------------
__device__ float g_phi[NN * F3];
__device__ float g_h[NN * FF];
__device__ float g_rbf[NRBF * EP];   // [k][pos], pos in padded CSR order
__device__ float g_dirx[EP];
__device__ float g_diry[EP];
__device__ float g_dirz[EP];
__device__ int   g_cnt[NN];
__device__ int   g_off[NN];          // even-aligned start per node
__device__ int   g_cur[NN];
__device__ int   g_order[EPAD];

// ---------------- CSR build ----------------
__global__ void k_init() {
    int i = blockIdx.x * blockDim.x + threadIdx.x;
    if (i < NN) g_cnt[i] = 0;
    if (i < EPAD) g_order[i] = -1;
}

__global__ void k_hist(const float* __restrict__ r) {
    int e = blockIdx.x * blockDim.x + threadIdx.x;
    if (e < EE) {
        int j = (int)r[e * 5 + 1];
        atomicAdd(&g_cnt[j], 1);
    }
}

// exclusive prefix over align2(cnt) so every node's range starts even
__global__ void k_scan() {
    __shared__ int part[1024];
    int t = threadIdx.x;
    const int CH = (NN + 1023) / 1024;
    int base = t * CH, sum = 0;
    for (int i = 0; i < CH; i++) {
        int idx = base + i;
        if (idx < NN) sum += (g_cnt[idx] + 1) & ~1;
    }
    part[t] = sum;
    __syncthreads();
    for (int off = 1; off < 1024; off <<= 1) {
        int v = (t >= off) ? part[t - off] : 0;
        __syncthreads();
        part[t] += v;
        __syncthreads();
    }
    int run = (t > 0) ? part[t - 1] : 0;
    for (int i = 0; i < CH; i++) {
        int idx = base + i;
        if (idx < NN) {
            g_off[idx] = run;
            g_cur[idx] = run;
            run += (g_cnt[idx] + 1) & ~1;
        }
    }
}

__global__ void k_fill(const float* __restrict__ r) {
    int e = blockIdx.x * blockDim.x + threadIdx.x;
    if (e < EE) {
        int j = (int)r[e * 5 + 1];
        int pos = atomicAdd(&g_cur[j], 1);
        g_order[pos] = e;
    }
}

// deterministic per-node order (atomic fill order varies per replay)
__global__ void k_sortlists() {
    int n = blockIdx.x * blockDim.x + threadIdx.x;
    if (n >= NN) return;
    int s0 = g_off[n], s1 = s0 + g_cnt[n];
    for (int i = s0 + 1; i < s1; i++) {
        int key = g_order[i];
        int j = i - 1;
        while (j >= s0 && g_order[j] > key) {
            g_order[j + 1] = g_order[j];
            j--;
        }
        g_order[j + 1] = key;
    }
}

// ---------------- per-edge precompute: rbf (sin recurrence) + dirn ----------------
__global__ void k_edge(const float* __restrict__ r) {
    int p = blockIdx.x * blockDim.x + threadIdx.x;
    if (p >= EPAD) return;
    int eid = g_order[p];
    if (eid < 0) return;   // pad slot: never read by k_main
    float rx = r[eid * 5 + 2];
    float ry = r[eid * 5 + 3];
    float rz = r[eid * 5 + 4];
    float z = fabsf(rz);
    float inv = 1.0f / (z + 1e-8f);
    float th = 0.6283185307179586f * z;   // pi/5 * z
    float s, c;
    sincosf(th, &s, &c);
    float twoc = 2.0f * c;
    float skm = 0.0f, sk = s;
#pragma unroll
    for (int k = 0; k < NRBF; k++) {
        g_rbf[k * EP + p] = sk * inv;
        float nxt = fmaf(twoc, sk, -skm);
        skm = sk; sk = nxt;
    }
    float nrm = sqrtf(rx * rx + ry * ry + rz * rz);
    float invn = 1.0f / (nrm + 1e-8f);
    g_dirx[p] = rx * invn;
    g_diry[p] = ry * invn;
    g_dirz[p] = rz * invn;
}

// ---------------- fp32 GEMM with memory-packed f32x2 inner loop ----------------
// BM=128 BN=64 BK=16, 256 threads, 8x4 microtile
template <bool SILU>
__global__ void __launch_bounds__(256) k_gemm(const float* __restrict__ A,
                                              const float* __restrict__ B,
                                              const float* __restrict__ bias,
                                              float* __restrict__ C,
                                              int M, int N, int K) {
    __shared__ u64 As2[16][130];   // dup-packed A, transposed: As2[k][row] = (a,a)
    __shared__ u64 Bs2[16][32];    // pair-packed B: Bs2[k][c] = (b[2c], b[2c+1])
    int t = threadIdx.x;
    int rowBase = blockIdx.y * 128;
    int colBase = blockIdx.x * 64;
    int tm = (t >> 4) << 3;    // 0..120 step 8
    int tn = (t & 15) << 2;    // 0..60  step 4
    u64 acc[8][2];
#pragma unroll
    for (int i = 0; i < 8; i++) { acc[i][0] = 0ull; acc[i][1] = 0ull; }
    int ar = t >> 2;
    int ak = (t & 3) << 2;
    int brow = t >> 4;
    int bc2 = (t & 15) << 1;   // u64 index of first B pair

    for (int kt = 0; kt < K; kt += 16) {
#pragma unroll
        for (int h = 0; h < 2; h++) {
            int row = ar + h * 64;
            int grow = rowBase + row;
            float4 a4 = make_float4(0.f, 0.f, 0.f, 0.f);
            if (grow < M) a4 = *(const float4*)&A[grow * K + kt + ak];
            As2[ak + 0][row] = pkdup(a4.x);
            As2[ak + 1][row] = pkdup(a4.y);
            As2[ak + 2][row] = pkdup(a4.z);
            As2[ak + 3][row] = pkdup(a4.w);
        }
        // float4 = two packed (lo,hi) pairs already
        *(float4*)&Bs2[brow][bc2] = *(const float4*)&B[(kt + brow) * N + colBase + (bc2 << 1)];
        __syncthreads();
#pragma unroll
        for (int k = 0; k < 16; k++) {
            u64 aa[8];
#pragma unroll
            for (int j = 0; j < 4; j++) {
                float4 q = *(float4*)&As2[k][tm + 2 * j];   // two dup u64s
                u64* qp = (u64*)&q;
                aa[2 * j] = qp[0];
                aa[2 * j + 1] = qp[1];
            }
            float4 bq = *(float4*)&Bs2[k][bc2 & 30];        // 2 packed pairs
            u64* bp = (u64*)&bq;
            u64 bb0 = bp[0], bb1 = bp[1];
#pragma unroll
            for (int i = 0; i < 8; i++) {
                acc[i][0] = f2fma(aa[i], bb0, acc[i][0]);
                acc[i][1] = f2fma(aa[i], bb1, acc[i][1]);
            }
            (void)0;
        }
        __syncthreads();
    }
#pragma unroll
    for (int i = 0; i < 8; i++) {
        int grow = rowBase + tm + i;
        if (grow < M) {
            float2 c0 = upk(acc[i][0]);
            float2 c1 = upk(acc[i][1]);
            float bv[4] = {c0.x, c0.y, c1.x, c1.y};
            float4 o;
#pragma unroll
            for (int j = 0; j < 4; j++) {
                float val = bv[j] + bias[colBase + tn + j];
                if (SILU) val = val / (1.0f + __expf(-val));
                bv[j] = val;
            }
            o.x = bv[0]; o.y = bv[1]; o.z = bv[2]; o.w = bv[3];
            *(float4*)&C[grow * N + colBase + tn] = o;
        }
    }
}

// ---------------- cutoff via MUFU: 0.5*(cos(pi*x/5)+1)*(x<5) ----------------
__device__ __forceinline__ float cw(float x) {
    float c = __cosf(x * 0.6283185307179586f);
    float w = fmaf(c, 0.5f, 0.5f);
    return (x < 5.0f) ? w : 0.0f;
}

// ---------------- main per-node kernel: edge-pair f32x2, memory-packed ----------------
__global__ void __launch_bounds__(128) k_main(const float* __restrict__ v,
                                              const float* __restrict__ Wr,
                                              const float* __restrict__ br,
                                              float* __restrict__ out) {
    int t = threadIdx.x;   // feature index
    u64 wr0d[NRBF], wr1d[NRBF], wr2d[NRBF];
#pragma unroll
    for (int k = 0; k < NRBF; k++) {
        wr0d[k] = pkdup(Wr[k * F3 + t]);
        wr1d[k] = pkdup(Wr[k * F3 + FF + t]);
        wr2d[k] = pkdup(Wr[k * F3 + 2 * FF + t]);
    }
    float br0 = br[t], br1 = br[FF + t], br2 = br[2 * FF + t];
    u64 br0d = pkdup(br0), br1d = pkdup(br1), br2d = pkdup(br2);

    for (int n = blockIdx.x; n < NN; n += gridDim.x) {
        int base = g_off[n];
        int cnt = g_cnt[n];
        u64 accA = 0ull, accB = 0ull, bx = 0ull, by = 0ull, bz = 0ull;
        int npairs = cnt >> 1;
        for (int i = 0; i < npairs; i++) {
            int p = base + (i << 1);
            u64 x0 = br0d, x1 = br1d, x2 = br2d;
#pragma unroll
            for (int k = 0; k < NRBF; k++) {
                u64 rr = *(const u64*)(g_rbf + k * EP + p);   // (rb[p],rb[p+1]) packed
                x0 = f2fma(rr, wr0d[k], x0);
                x1 = f2fma(rr, wr1d[k], x1);
                x2 = f2fma(rr, wr2d[k], x2);
            }
            float2 v0 = upk(x0), v1 = upk(x1), v2 = upk(x2);
            u64 W0 = pk2(cw(v0.x), cw(v0.y));
            u64 W1 = pk2(cw(v1.x), cw(v1.y));
            u64 W2 = pk2(cw(v2.x), cw(v2.y));
            accA = f2add(accA, W0);
            accB = f2add(accB, W1);
            bx = f2fma(W2, *(const u64*)(g_dirx + p), bx);
            by = f2fma(W2, *(const u64*)(g_diry + p), by);
            bz = f2fma(W2, *(const u64*)(g_dirz + p), bz);
        }
        float2 rA = upk(accA), rB = upk(accB);
        float2 rx = upk(bx), ry = upk(by), rz = upk(bz);
        float a1 = rA.x + rA.y;
        float a2 = rB.x + rB.y;
        float cx = rx.x + rx.y;
        float cy = ry.x + ry.y;
        float cz = rz.x + rz.y;
        if (cnt & 1) {
            int p = base + cnt - 1;
            float x0 = br0, x1 = br1, x2 = br2;
#pragma unroll
            for (int k = 0; k < NRBF; k++) {
                float rb = g_rbf[k * EP + p];
                x0 = fmaf(rb, upk(wr0d[k]).x, x0);
                x1 = fmaf(rb, upk(wr1d[k]).x, x1);
                x2 = fmaf(rb, upk(wr2d[k]).x, x2);
            }
            float W0 = cw(x0), W1 = cw(x1), W2 = cw(x2);
            a1 += W0; a2 += W1;
            cx = fmaf(W2, g_dirx[p], cx);
            cy = fmaf(W2, g_diry[p], cy);
            cz = fmaf(W2, g_dirz[p], cz);
        }
        float ph1 = g_phi[n * F3 + t];
        float ph2 = g_phi[n * F3 + FF + t];
        float ph3 = g_phi[n * F3 + 2 * FF + t];
        int nf = n * FF + t;
        float vx = v[nf * 3 + 0], vy = v[nf * 3 + 1], vz = v[nf * 3 + 2];
        float s1v = ph1 * a1;
        out[nf * 3 + 0] = fmaf(vx, s1v, ph3 * cx);
        out[nf * 3 + 1] = fmaf(vy, s1v, ph3 * cy);
        out[nf * 3 + 2] = fmaf(vz, s1v, ph3 * cz);
        out[NN * F3 + nf] = ph2 * a2;
    }
}

// ---------------- launch ----------------
extern "C" void kernel_launch(void* const* d_in, const int* in_sizes, int n_in,
                              void* d_out, int out_size) {
    (void)in_sizes; (void)n_in; (void)out_size;
    const float* v  = (const float*)d_in[0];
    const float* s  = (const float*)d_in[1];
    const float* r  = (const float*)d_in[2];
    const float* W1 = (const float*)d_in[3];
    const float* b1 = (const float*)d_in[4];
    const float* W2 = (const float*)d_in[5];
    const float* b2 = (const float*)d_in[6];
    const float* Wr = (const float*)d_in[7];
    const float* br = (const float*)d_in[8];
    float* out = (float*)d_out;

    void* q;
    cudaGetSymbolAddress(&q, g_h);
    float* hptr = (float*)q;
    cudaGetSymbolAddress(&q, g_phi);
    float* pptr = (float*)q;

    k_init<<<(EPAD + 255) / 256, 256>>>();
    k_hist<<<(EE + 255) / 256, 256>>>(r);
    k_scan<<<1, 1024>>>();
    k_fill<<<(EE + 255) / 256, 256>>>(r);
    k_sortlists<<<(NN + 127) / 128, 128>>>();
    k_edge<<<(EPAD + 127) / 128, 128>>>(r);
    {
        dim3 g1(FF / 64, (NN + 127) / 128);
        k_gemm<true><<<g1, 256>>>(s, W1, b1, hptr, NN, FF, FF);
        dim3 g2(F3 / 64, (NN + 127) / 128);
        k_gemm<false><<<g2, 256>>>(hptr, W2, b2, pptr, NN, F3, FF);
    }
    k_main<<<2048, 128>>>(v, Wr, br, out);
}

// round 4
// speedup vs baseline: 1.3669x; 1.0304x over previous
#include <cuda_runtime.h>
#include <math.h>

#define NN 50000
#define EE 400000
#define FF 128
#define F3 384
#define NRBF 20
#define EPAD (EE + NN)          // CSR positions incl. per-node even-alignment pads
#define EP 450560               // padded stride for rbf/dirn arrays (>= EPAD+32, even)
#define CHUNK 16                // pairs staged per smem tile

typedef unsigned long long u64;

// ---------------- f32x2 packed helpers ----------------
__device__ __forceinline__ u64 pk2(float a, float b) {
    u64 r; asm("mov.b64 %0,{%1,%2};" : "=l"(r) : "f"(a), "f"(b)); return r;
}
__device__ __forceinline__ u64 pkdup(float a) {
    u64 r; asm("mov.b64 %0,{%1,%1};" : "=l"(r) : "f"(a)); return r;
}
__device__ __forceinline__ float2 upk(u64 v) {
    float2 f; asm("mov.b64 {%0,%1},%2;" : "=f"(f.x), "=f"(f.y) : "l"(v)); return f;
}
__device__ __forceinline__ u64 f2fma(u64 a, u64 b, u64 c) {
    u64 d; asm("fma.rn.f32x2 %0,%1,%2,%3;" : "=l"(d) : "l"(a), "l"(b), "l"(c)); return d;
}
__device__ __forceinline__ u64 f2add(u64 a, u64 b) {
    u64 d; asm("add.rn.f32x2 %0,%1,%2;" : "=l"(d) : "l"(a), "l"(b)); return d;
}

// ---------------- scratch ----------------
__device__ float g_phi[NN * F3];
__device__ float g_h[NN * FF];
__device__ float g_rbf[NRBF * EP];   // [k][pos], pos in padded CSR order
__device__ float g_dirx[EP];
__device__ float g_diry[EP];
__device__ float g_dirz[EP];
__device__ int   g_cnt[NN];
__device__ int   g_off[NN];          // even-aligned start per node
__device__ int   g_cur[NN];
__device__ int   g_order[EPAD];

// ---------------- CSR build ----------------
__global__ void k_init() {
    int i = blockIdx.x * blockDim.x + threadIdx.x;
    if (i < NN) g_cnt[i] = 0;
    if (i < EPAD) g_order[i] = -1;
}

__global__ void k_hist(const float* __restrict__ r) {
    int e = blockIdx.x * blockDim.x + threadIdx.x;
    if (e < EE) {
        int j = (int)r[e * 5 + 1];
        atomicAdd(&g_cnt[j], 1);
    }
}

// exclusive prefix over align2(cnt) so every node's range starts even
__global__ void k_scan() {
    __shared__ int part[1024];
    int t = threadIdx.x;
    const int CH = (NN + 1023) / 1024;
    int base = t * CH, sum = 0;
    for (int i = 0; i < CH; i++) {
        int idx = base + i;
        if (idx < NN) sum += (g_cnt[idx] + 1) & ~1;
    }
    part[t] = sum;
    __syncthreads();
    for (int off = 1; off < 1024; off <<= 1) {
        int v = (t >= off) ? part[t - off] : 0;
        __syncthreads();
        part[t] += v;
        __syncthreads();
    }
    int run = (t > 0) ? part[t - 1] : 0;
    for (int i = 0; i < CH; i++) {
        int idx = base + i;
        if (idx < NN) {
            g_off[idx] = run;
            g_cur[idx] = run;
            run += (g_cnt[idx] + 1) & ~1;
        }
    }
}

__global__ void k_fill(const float* __restrict__ r) {
    int e = blockIdx.x * blockDim.x + threadIdx.x;
    if (e < EE) {
        int j = (int)r[e * 5 + 1];
        int pos = atomicAdd(&g_cur[j], 1);
        g_order[pos] = e;
    }
}

// deterministic per-node order (atomic fill order varies per replay)
__global__ void k_sortlists() {
    int n = blockIdx.x * blockDim.x + threadIdx.x;
    if (n >= NN) return;
    int s0 = g_off[n], s1 = s0 + g_cnt[n];
    for (int i = s0 + 1; i < s1; i++) {
        int key = g_order[i];
        int j = i - 1;
        while (j >= s0 && g_order[j] > key) {
            g_order[j + 1] = g_order[j];
            j--;
        }
        g_order[j + 1] = key;
    }
}

// ---------------- per-edge precompute: rbf (sin recurrence) + dirn ----------------
// pad slots (eid<0) get ZEROS so k_main's packed path can read them safely
__global__ void k_edge(const float* __restrict__ r) {
    int p = blockIdx.x * blockDim.x + threadIdx.x;
    if (p >= EPAD) return;
    int eid = g_order[p];
    if (eid < 0) {
#pragma unroll
        for (int k = 0; k < NRBF; k++) g_rbf[k * EP + p] = 0.0f;
        g_dirx[p] = 0.0f; g_diry[p] = 0.0f; g_dirz[p] = 0.0f;
        return;
    }
    float rx = r[eid * 5 + 2];
    float ry = r[eid * 5 + 3];
    float rz = r[eid * 5 + 4];
    float z = fabsf(rz);
    float inv = 1.0f / (z + 1e-8f);
    float th = 0.6283185307179586f * z;   // pi/5 * z
    float s, c;
    sincosf(th, &s, &c);
    float twoc = 2.0f * c;
    float skm = 0.0f, sk = s;
#pragma unroll
    for (int k = 0; k < NRBF; k++) {
        g_rbf[k * EP + p] = sk * inv;
        float nxt = fmaf(twoc, sk, -skm);
        skm = sk; sk = nxt;
    }
    float nrm = sqrtf(rx * rx + ry * ry + rz * rz);
    float invn = 1.0f / (nrm + 1e-8f);
    g_dirx[p] = rx * invn;
    g_diry[p] = ry * invn;
    g_dirz[p] = rz * invn;
}

// ---------------- fp32 GEMM with memory-packed f32x2 inner loop ----------------
template <bool SILU>
__global__ void __launch_bounds__(256) k_gemm(const float* __restrict__ A,
                                              const float* __restrict__ B,
                                              const float* __restrict__ bias,
                                              float* __restrict__ C,
                                              int M, int N, int K) {
    __shared__ u64 As2[16][130];   // dup-packed A, transposed
    __shared__ u64 Bs2[16][32];    // pair-packed B
    int t = threadIdx.x;
    int rowBase = blockIdx.y * 128;
    int colBase = blockIdx.x * 64;
    int tm = (t >> 4) << 3;
    int tn = (t & 15) << 2;
    u64 acc[8][2];
#pragma unroll
    for (int i = 0; i < 8; i++) { acc[i][0] = 0ull; acc[i][1] = 0ull; }
    int ar = t >> 2;
    int ak = (t & 3) << 2;
    int brow = t >> 4;
    int bc2 = (t & 15) << 1;

    for (int kt = 0; kt < K; kt += 16) {
#pragma unroll
        for (int h = 0; h < 2; h++) {
            int row = ar + h * 64;
            int grow = rowBase + row;
            float4 a4 = make_float4(0.f, 0.f, 0.f, 0.f);
            if (grow < M) a4 = *(const float4*)&A[grow * K + kt + ak];
            As2[ak + 0][row] = pkdup(a4.x);
            As2[ak + 1][row] = pkdup(a4.y);
            As2[ak + 2][row] = pkdup(a4.z);
            As2[ak + 3][row] = pkdup(a4.w);
        }
        *(float4*)&Bs2[brow][bc2] = *(const float4*)&B[(kt + brow) * N + colBase + (bc2 << 1)];
        __syncthreads();
#pragma unroll
        for (int k = 0; k < 16; k++) {
            u64 aa[8];
#pragma unroll
            for (int j = 0; j < 4; j++) {
                float4 q = *(float4*)&As2[k][tm + 2 * j];
                u64* qp = (u64*)&q;
                aa[2 * j] = qp[0];
                aa[2 * j + 1] = qp[1];
            }
            float4 bq = *(float4*)&Bs2[k][bc2 & 30];
            u64* bp = (u64*)&bq;
            u64 bb0 = bp[0], bb1 = bp[1];
#pragma unroll
            for (int i = 0; i < 8; i++) {
                acc[i][0] = f2fma(aa[i], bb0, acc[i][0]);
                acc[i][1] = f2fma(aa[i], bb1, acc[i][1]);
            }
        }
        __syncthreads();
    }
#pragma unroll
    for (int i = 0; i < 8; i++) {
        int grow = rowBase + tm + i;
        if (grow < M) {
            float2 c0 = upk(acc[i][0]);
            float2 c1 = upk(acc[i][1]);
            float bv[4] = {c0.x, c0.y, c1.x, c1.y};
            float4 o;
#pragma unroll
            for (int j = 0; j < 4; j++) {
                float val = bv[j] + bias[colBase + tn + j];
                if (SILU) val = val / (1.0f + __expf(-val));
                bv[j] = val;
            }
            o.x = bv[0]; o.y = bv[1]; o.z = bv[2]; o.w = bv[3];
            *(float4*)&C[grow * N + colBase + tn] = o;
        }
    }
}

// ---------------- cutoff via MUFU: 0.5*(cos(pi*x/5)+1)*(x<5) ----------------
__device__ __forceinline__ float cw(float x) {
    float c = __cosf(x * 0.6283185307179586f);
    float w = fmaf(c, 0.5f, 0.5f);
    return (x < 5.0f) ? w : 0.0f;
}

// ---------------- main per-node kernel: smem-staged edge data, f32x2 ----------------
__global__ void __launch_bounds__(128) k_main(const float* __restrict__ v,
                                              const float* __restrict__ Wr,
                                              const float* __restrict__ br,
                                              float* __restrict__ out) {
    __shared__ u64 sm[23][CHUNK];   // rows 0..19: rbf pairs; 20..22: dirx/diry/dirz pairs
    int t = threadIdx.x;            // feature index

    u64 wr0d[NRBF], wr1d[NRBF], wr2d[NRBF];
#pragma unroll
    for (int k = 0; k < NRBF; k++) {
        wr0d[k] = pkdup(Wr[k * F3 + t]);
        wr1d[k] = pkdup(Wr[k * F3 + FF + t]);
        wr2d[k] = pkdup(Wr[k * F3 + 2 * FF + t]);
    }
    u64 br0d = pkdup(br[t]), br1d = pkdup(br[FF + t]), br2d = pkdup(br[2 * FF + t]);

    for (int n = blockIdx.x; n < NN; n += gridDim.x) {
        int base = g_off[n];
        int cnt = g_cnt[n];
        int npairs = (cnt + 1) >> 1;
        u64 accA = 0ull, accB = 0ull, bx = 0ull, by = 0ull, bz = 0ull;

        for (int cs = 0; cs < npairs; cs += CHUNK) {
            int nc = npairs - cs; if (nc > CHUNK) nc = CHUNK;
            __syncthreads();   // previous tile fully consumed
            // cooperative coalesced load of 23 rows x CHUNK u64 (OOB-in-array safe)
            {
                int pbase = base + (cs << 1);           // even
#pragma unroll
                for (int idx = 0; idx < 3; idx++) {
                    int q = t + idx * 128;
                    if (q < 23 * CHUNK) {
                        int j = q >> 4;       // row
                        int i = q & 15;       // pair within chunk
                        const float* rowp;
                        if (j < NRBF)      rowp = g_rbf + j * EP + pbase;
                        else if (j == 20)  rowp = g_dirx + pbase;
                        else if (j == 21)  rowp = g_diry + pbase;
                        else               rowp = g_dirz + pbase;
                        sm[j][i] = *(const u64*)(rowp + (i << 1));
                    }
                }
            }
            __syncthreads();
            for (int i = 0; i < nc; i++) {
                u64 x0 = br0d, x1 = br1d, x2 = br2d;
#pragma unroll
                for (int k = 0; k < NRBF; k++) {
                    u64 rr = sm[k][i];
                    x0 = f2fma(rr, wr0d[k], x0);
                    x1 = f2fma(rr, wr1d[k], x1);
                    x2 = f2fma(rr, wr2d[k], x2);
                }
                float2 v0 = upk(x0), v1 = upk(x1), v2 = upk(x2);
                u64 W0 = pk2(cw(v0.x), cw(v0.y));
                u64 W1 = pk2(cw(v1.x), cw(v1.y));
                u64 W2 = pk2(cw(v2.x), cw(v2.y));
                // mask lane1 of the last pair when cnt is odd (pad slot)
                u64 m = (((cs + i) << 1) + 1 < cnt) ? ~0ull : 0xFFFFFFFFull;
                accA = f2add(accA, W0 & m);
                accB = f2add(accB, W1 & m);
                bx = f2fma(W2, sm[20][i], bx);   // pad dirn == 0 -> self-masked
                by = f2fma(W2, sm[21][i], by);
                bz = f2fma(W2, sm[22][i], bz);
            }
        }
        float2 rA = upk(accA), rB = upk(accB);
        float2 rx = upk(bx), ry = upk(by), rz = upk(bz);
        float a1 = rA.x + rA.y;
        float a2 = rB.x + rB.y;
        float cx = rx.x + rx.y;
        float cy = ry.x + ry.y;
        float cz = rz.x + rz.y;

        float ph1 = g_phi[n * F3 + t];
        float ph2 = g_phi[n * F3 + FF + t];
        float ph3 = g_phi[n * F3 + 2 * FF + t];
        int nf = n * FF + t;
        float vx = v[nf * 3 + 0], vy = v[nf * 3 + 1], vz = v[nf * 3 + 2];
        float s1v = ph1 * a1;
        out[nf * 3 + 0] = fmaf(vx, s1v, ph3 * cx);
        out[nf * 3 + 1] = fmaf(vy, s1v, ph3 * cy);
        out[nf * 3 + 2] = fmaf(vz, s1v, ph3 * cz);
        out[NN * F3 + nf] = ph2 * a2;
    }
}

// ---------------- launch ----------------
extern "C" void kernel_launch(void* const* d_in, const int* in_sizes, int n_in,
                              void* d_out, int out_size) {
    (void)in_sizes; (void)n_in; (void)out_size;
    const float* v  = (const float*)d_in[0];
    const float* s  = (const float*)d_in[1];
    const float* r  = (const float*)d_in[2];
    const float* W1 = (const float*)d_in[3];
    const float* b1 = (const float*)d_in[4];
    const float* W2 = (const float*)d_in[5];
    const float* b2 = (const float*)d_in[6];
    const float* Wr = (const float*)d_in[7];
    const float* br = (const float*)d_in[8];
    float* out = (float*)d_out;

    void* q;
    cudaGetSymbolAddress(&q, g_h);
    float* hptr = (float*)q;
    cudaGetSymbolAddress(&q, g_phi);
    float* pptr = (float*)q;

    k_init<<<(EPAD + 255) / 256, 256>>>();
    k_hist<<<(EE + 255) / 256, 256>>>(r);
    k_scan<<<1, 1024>>>();
    // GEMMs moved before CSR-fill so the ncu capture slot (launch idx 3) profiles gemm1
    {
        dim3 g1(FF / 64, (NN + 127) / 128);
        k_gemm<true><<<g1, 256>>>(s, W1, b1, hptr, NN, FF, FF);
        dim3 g2(F3 / 64, (NN + 127) / 128);
        k_gemm<false><<<g2, 256>>>(hptr, W2, b2, pptr, NN, F3, FF);
    }
    k_fill<<<(EE + 255) / 256, 256>>>(r);
    k_sortlists<<<(NN + 127) / 128, 128>>>();
    k_edge<<<(EPAD + 127) / 128, 128>>>(r);
    k_main<<<2048, 128>>>(v, Wr, br, out);
}

// round 5
// speedup vs baseline: 1.3959x; 1.0212x over previous
#include <cuda_runtime.h>
#include <math.h>

#define NN 50000
#define EE 400000
#define FF 128
#define F3 384
#define NRBF 20
#define EPAD (EE + NN)          // CSR positions incl. per-node even-alignment pads
#define EP 450560               // padded stride for rbf/dirn arrays (>= EPAD+64, even)
#define CHUNK 32                // pairs staged per smem tile in k_main

typedef unsigned long long u64;

// ---------------- f32x2 packed helpers ----------------
__device__ __forceinline__ u64 pk2(float a, float b) {
    u64 r; asm("mov.b64 %0,{%1,%2};" : "=l"(r) : "f"(a), "f"(b)); return r;
}
__device__ __forceinline__ u64 pkdup(float a) {
    u64 r; asm("mov.b64 %0,{%1,%1};" : "=l"(r) : "f"(a)); return r;
}
__device__ __forceinline__ float2 upk(u64 v) {
    float2 f; asm("mov.b64 {%0,%1},%2;" : "=f"(f.x), "=f"(f.y) : "l"(v)); return f;
}
__device__ __forceinline__ u64 f2fma(u64 a, u64 b, u64 c) {
    u64 d; asm("fma.rn.f32x2 %0,%1,%2,%3;" : "=l"(d) : "l"(a), "l"(b), "l"(c)); return d;
}
__device__ __forceinline__ u64 f2add(u64 a, u64 b) {
    u64 d; asm("add.rn.f32x2 %0,%1,%2;" : "=l"(d) : "l"(a), "l"(b)); return d;
}

// ---------------- scratch ----------------
__device__ float g_phi[NN * F3];
__device__ float g_h[NN * FF];
__device__ float g_rbf[NRBF * EP];   // [k][pos], pos in padded CSR order
__device__ float g_dirx[EP];
__device__ float g_diry[EP];
__device__ float g_dirz[EP];
__device__ int   g_cnt[NN];
__device__ int   g_off[NN];          // even-aligned start per node
__device__ int   g_cur[NN];
__device__ int   g_order[EPAD];

// ---------------- CSR build ----------------
__global__ void k_init() {
    int i = blockIdx.x * blockDim.x + threadIdx.x;
    if (i < NN) g_cnt[i] = 0;
    if (i < EPAD) g_order[i] = -1;
}

__global__ void k_hist(const float* __restrict__ r) {
    int e = blockIdx.x * blockDim.x + threadIdx.x;
    if (e < EE) {
        int j = (int)r[e * 5 + 1];
        atomicAdd(&g_cnt[j], 1);
    }
}

// exclusive prefix over align2(cnt) so every node's range starts even
__global__ void k_scan() {
    __shared__ int part[1024];
    int t = threadIdx.x;
    const int CH = (NN + 1023) / 1024;
    int base = t * CH, sum = 0;
    for (int i = 0; i < CH; i++) {
        int idx = base + i;
        if (idx < NN) sum += (g_cnt[idx] + 1) & ~1;
    }
    part[t] = sum;
    __syncthreads();
    for (int off = 1; off < 1024; off <<= 1) {
        int v = (t >= off) ? part[t - off] : 0;
        __syncthreads();
        part[t] += v;
        __syncthreads();
    }
    int run = (t > 0) ? part[t - 1] : 0;
    for (int i = 0; i < CH; i++) {
        int idx = base + i;
        if (idx < NN) {
            g_off[idx] = run;
            g_cur[idx] = run;
            run += (g_cnt[idx] + 1) & ~1;
        }
    }
}

__global__ void k_fill(const float* __restrict__ r) {
    int e = blockIdx.x * blockDim.x + threadIdx.x;
    if (e < EE) {
        int j = (int)r[e * 5 + 1];
        int pos = atomicAdd(&g_cur[j], 1);
        g_order[pos] = e;
    }
}

// deterministic per-node order (atomic fill order varies per replay)
__global__ void k_sortlists() {
    int n = blockIdx.x * blockDim.x + threadIdx.x;
    if (n >= NN) return;
    int s0 = g_off[n], s1 = s0 + g_cnt[n];
    for (int i = s0 + 1; i < s1; i++) {
        int key = g_order[i];
        int j = i - 1;
        while (j >= s0 && g_order[j] > key) {
            g_order[j + 1] = g_order[j];
            j--;
        }
        g_order[j + 1] = key;
    }
}

// ---------------- per-edge precompute: rbf (sin recurrence) + dirn ----------------
// pad slots (eid<0) get ZEROS so k_main's packed path can read them safely
__global__ void k_edge(const float* __restrict__ r) {
    int p = blockIdx.x * blockDim.x + threadIdx.x;
    if (p >= EPAD) return;
    int eid = g_order[p];
    if (eid < 0) {
#pragma unroll
        for (int k = 0; k < NRBF; k++) g_rbf[k * EP + p] = 0.0f;
        g_dirx[p] = 0.0f; g_diry[p] = 0.0f; g_dirz[p] = 0.0f;
        return;
    }
    float rx = r[eid * 5 + 2];
    float ry = r[eid * 5 + 3];
    float rz = r[eid * 5 + 4];
    float z = fabsf(rz);
    float inv = 1.0f / (z + 1e-8f);
    float th = 0.6283185307179586f * z;   // pi/5 * z
    float s, c;
    sincosf(th, &s, &c);
    float twoc = 2.0f * c;
    float skm = 0.0f, sk = s;
#pragma unroll
    for (int k = 0; k < NRBF; k++) {
        g_rbf[k * EP + p] = sk * inv;
        float nxt = fmaf(twoc, sk, -skm);
        skm = sk; sk = nxt;
    }
    float nrm = sqrtf(rx * rx + ry * ry + rz * rz);
    float invn = 1.0f / (nrm + 1e-8f);
    g_dirx[p] = rx * invn;
    g_diry[p] = ry * invn;
    g_dirz[p] = rz * invn;
}

// ---------------- fp32 GEMM: BM=128 BN=128 BK=16, 8x8 microtile, f32x2 math ----------------
// A in smem as plain float (transposed), dup-pack in registers (ALU pipe).
// Per k-iter per thread: 4x LDS.128 (64B) -> 32 FFMA2: exactly at smem BW.
template <bool SILU>
__global__ void __launch_bounds__(256) k_gemm(const float* __restrict__ A,
                                              const float* __restrict__ B,
                                              const float* __restrict__ bias,
                                              float* __restrict__ C,
                                              int M, int N, int K) {
    __shared__ float As[16][136];   // [k][row], padded
    __shared__ float Bs[16][128];   // [k][col]
    int t = threadIdx.x;
    int rowBase = blockIdx.y * 128;
    int colBase = blockIdx.x * 128;
    int tm = (t >> 4) << 3;     // 0..120 step 8
    int tn = (t & 15) << 3;     // 0..120 step 8

    u64 acc[8][4];
#pragma unroll
    for (int i = 0; i < 8; i++)
#pragma unroll
        for (int j = 0; j < 4; j++) acc[i][j] = 0ull;

    for (int kt = 0; kt < K; kt += 16) {
        // load A tile: 128 rows x 16 cols = 512 float4; thread does 2
#pragma unroll
        for (int h = 0; h < 2; h++) {
            int slot = t * 2 + h;          // 0..511
            int row = slot >> 2;
            int kq = (slot & 3) << 2;
            int grow = rowBase + row;
            float4 a4 = make_float4(0.f, 0.f, 0.f, 0.f);
            if (grow < M) a4 = *(const float4*)&A[grow * K + kt + kq];
            As[kq + 0][row] = a4.x;
            As[kq + 1][row] = a4.y;
            As[kq + 2][row] = a4.z;
            As[kq + 3][row] = a4.w;
        }
        // load B tile: 16 rows x 128 cols = 512 float4; thread does 2
#pragma unroll
        for (int h = 0; h < 2; h++) {
            int slot = t * 2 + h;          // 0..511
            int row = slot >> 5;
            int c4 = (slot & 31) << 2;
            *(float4*)&Bs[row][c4] = *(const float4*)&B[(kt + row) * N + colBase + c4];
        }
        __syncthreads();
#pragma unroll
        for (int k = 0; k < 16; k++) {
            float4 a0 = *(float4*)&As[k][tm];
            float4 a1 = *(float4*)&As[k][tm + 4];
            float4 b0 = *(float4*)&Bs[k][tn];
            float4 b1 = *(float4*)&Bs[k][tn + 4];
            u64 aa[8];
            aa[0] = pkdup(a0.x); aa[1] = pkdup(a0.y);
            aa[2] = pkdup(a0.z); aa[3] = pkdup(a0.w);
            aa[4] = pkdup(a1.x); aa[5] = pkdup(a1.y);
            aa[6] = pkdup(a1.z); aa[7] = pkdup(a1.w);
            u64 bb[4];
            bb[0] = pk2(b0.x, b0.y); bb[1] = pk2(b0.z, b0.w);
            bb[2] = pk2(b1.x, b1.y); bb[3] = pk2(b1.z, b1.w);
#pragma unroll
            for (int i = 0; i < 8; i++)
#pragma unroll
                for (int j = 0; j < 4; j++)
                    acc[i][j] = f2fma(aa[i], bb[j], acc[i][j]);
        }
        __syncthreads();
    }
    // epilogue
    float bias8[8];
#pragma unroll
    for (int j = 0; j < 8; j++) bias8[j] = bias[colBase + tn + j];
#pragma unroll
    for (int i = 0; i < 8; i++) {
        int grow = rowBase + tm + i;
        if (grow < M) {
            float o[8];
#pragma unroll
            for (int j = 0; j < 4; j++) {
                float2 c2 = upk(acc[i][j]);
                o[2 * j] = c2.x;
                o[2 * j + 1] = c2.y;
            }
#pragma unroll
            for (int j = 0; j < 8; j++) {
                float val = o[j] + bias8[j];
                if (SILU) val = val / (1.0f + __expf(-val));
                o[j] = val;
            }
            *(float4*)&C[grow * N + colBase + tn] = make_float4(o[0], o[1], o[2], o[3]);
            *(float4*)&C[grow * N + colBase + tn + 4] = make_float4(o[4], o[5], o[6], o[7]);
        }
    }
}

// ---------------- cutoff via MUFU: 0.5*(cos(pi*x/5)+1)*(x<5) ----------------
__device__ __forceinline__ float cw(float x) {
    float c = __cosf(x * 0.6283185307179586f);
    float w = fmaf(c, 0.5f, 0.5f);
    return (x < 5.0f) ? w : 0.0f;
}

// ---------------- main per-node kernel: smem-staged edge data, f32x2 ----------------
__global__ void __launch_bounds__(128) k_main(const float* __restrict__ v,
                                              const float* __restrict__ Wr,
                                              const float* __restrict__ br,
                                              float* __restrict__ out) {
    __shared__ u64 sm[23][CHUNK];   // rows 0..19: rbf pairs; 20..22: dirx/diry/dirz pairs
    int t = threadIdx.x;            // feature index

    u64 wr0d[NRBF], wr1d[NRBF], wr2d[NRBF];
#pragma unroll
    for (int k = 0; k < NRBF; k++) {
        wr0d[k] = pkdup(Wr[k * F3 + t]);
        wr1d[k] = pkdup(Wr[k * F3 + FF + t]);
        wr2d[k] = pkdup(Wr[k * F3 + 2 * FF + t]);
    }
    u64 br0d = pkdup(br[t]), br1d = pkdup(br[FF + t]), br2d = pkdup(br[2 * FF + t]);

    for (int n = blockIdx.x; n < NN; n += gridDim.x) {
        int base = g_off[n];
        int cnt = g_cnt[n];
        int npairs = (cnt + 1) >> 1;
        u64 accA = 0ull, accB = 0ull, bx = 0ull, by = 0ull, bz = 0ull;

        for (int cs = 0; cs < npairs; cs += CHUNK) {
            int nc = npairs - cs; if (nc > CHUNK) nc = CHUNK;
            __syncthreads();   // previous tile fully consumed
            // cooperative coalesced load of 23 rows x CHUNK u64
            {
                int pbase = base + (cs << 1);           // even
#pragma unroll
                for (int idx = 0; idx < 6; idx++) {
                    int q = t + idx * 128;
                    if (q < 23 * CHUNK) {
                        int j = q >> 5;       // row
                        int i = q & 31;       // pair within chunk
                        const float* rowp;
                        if (j < NRBF)      rowp = g_rbf + j * EP + pbase;
                        else if (j == 20)  rowp = g_dirx + pbase;
                        else if (j == 21)  rowp = g_diry + pbase;
                        else               rowp = g_dirz + pbase;
                        sm[j][i] = *(const u64*)(rowp + (i << 1));
                    }
                }
            }
            __syncthreads();
            for (int i = 0; i < nc; i++) {
                u64 x0 = br0d, x1 = br1d, x2 = br2d;
#pragma unroll
                for (int k = 0; k < NRBF; k++) {
                    u64 rr = sm[k][i];
                    x0 = f2fma(rr, wr0d[k], x0);
                    x1 = f2fma(rr, wr1d[k], x1);
                    x2 = f2fma(rr, wr2d[k], x2);
                }
                float2 v0 = upk(x0), v1 = upk(x1), v2 = upk(x2);
                u64 W0 = pk2(cw(v0.x), cw(v0.y));
                u64 W1 = pk2(cw(v1.x), cw(v1.y));
                u64 W2 = pk2(cw(v2.x), cw(v2.y));
                // mask lane1 of the last pair when cnt is odd (pad slot)
                u64 m = (((cs + i) << 1) + 1 < cnt) ? ~0ull : 0xFFFFFFFFull;
                accA = f2add(accA, W0 & m);
                accB = f2add(accB, W1 & m);
                bx = f2fma(W2, sm[20][i], bx);   // pad dirn == 0 -> self-masked
                by = f2fma(W2, sm[21][i], by);
                bz = f2fma(W2, sm[22][i], bz);
            }
        }
        float2 rA = upk(accA), rB = upk(accB);
        float2 rx = upk(bx), ry = upk(by), rz = upk(bz);
        float a1 = rA.x + rA.y;
        float a2 = rB.x + rB.y;
        float cx = rx.x + rx.y;
        float cy = ry.x + ry.y;
        float cz = rz.x + rz.y;

        float ph1 = g_phi[n * F3 + t];
        float ph2 = g_phi[n * F3 + FF + t];
        float ph3 = g_phi[n * F3 + 2 * FF + t];
        int nf = n * FF + t;
        float vx = v[nf * 3 + 0], vy = v[nf * 3 + 1], vz = v[nf * 3 + 2];
        float s1v = ph1 * a1;
        out[nf * 3 + 0] = fmaf(vx, s1v, ph3 * cx);
        out[nf * 3 + 1] = fmaf(vy, s1v, ph3 * cy);
        out[nf * 3 + 2] = fmaf(vz, s1v, ph3 * cz);
        out[NN * F3 + nf] = ph2 * a2;
    }
}

// ---------------- launch ----------------
extern "C" void kernel_launch(void* const* d_in, const int* in_sizes, int n_in,
                              void* d_out, int out_size) {
    (void)in_sizes; (void)n_in; (void)out_size;
    const float* v  = (const float*)d_in[0];
    const float* s  = (const float*)d_in[1];
    const float* r  = (const float*)d_in[2];
    const float* W1 = (const float*)d_in[3];
    const float* b1 = (const float*)d_in[4];
    const float* W2 = (const float*)d_in[5];
    const float* b2 = (const float*)d_in[6];
    const float* Wr = (const float*)d_in[7];
    const float* br = (const float*)d_in[8];
    float* out = (float*)d_out;

    void* q;
    cudaGetSymbolAddress(&q, g_h);
    float* hptr = (float*)q;
    cudaGetSymbolAddress(&q, g_phi);
    float* pptr = (float*)q;

    k_init<<<(EPAD + 255) / 256, 256>>>();
    k_hist<<<(EE + 255) / 256, 256>>>(r);
    k_scan<<<1, 1024>>>();
    // GEMMs here so ncu capture slot (launch idx 3) stays on gemm1
    {
        dim3 g1(FF / 128, (NN + 127) / 128);
        k_gemm<true><<<g1, 256>>>(s, W1, b1, hptr, NN, FF, FF);
        dim3 g2(F3 / 128, (NN + 127) / 128);
        k_gemm<false><<<g2, 256>>>(hptr, W2, b2, pptr, NN, F3, FF);
    }
    k_fill<<<(EE + 255) / 256, 256>>>(r);
    k_sortlists<<<(NN + 127) / 128, 128>>>();
    k_edge<<<(EPAD + 127) / 128, 128>>>(r);
    k_main<<<2048, 128>>>(v, Wr, br, out);
}